// round 10
// baseline (speedup 1.0000x reference)
#include <cuda_runtime.h>
#include <cuda_fp16.h>
#include <cuda_bf16.h>
#include <cuda_fp8.h>
#include <cstdint>

#define NMAX 20000
#define EMAX 320000
#define SB   148            // grid-resident block count

__device__ float   g_X[NMAX * 512];      // fp32 X[n][h*128+o] (head-mean)
__device__ uint8_t g_Xf8[NMAX * 512];    // e4m3 (x*32) copy for gathers
__device__ float   g_sprm[NMAX * 8];     // [n*8+h]=s_src, [n*8+4+h]=s_dst
__device__ float   g_sc[EMAX * 4];       // exp(score), slot-major float4
__device__ int2    g_perm[EMAX];         // sorted-by-src {src, dst}
__device__ int     g_cnt[NMAX];          // histogram -> cursor
__device__ int     g_start[NMAX + 1];    // bucket starts
__device__ int     g_bsum[SB];           // per-block sums for scan
__device__ float   g_hsum[4];
__device__ int     g_is64;
__device__ volatile int g_barcnt[8];     // spin-barrier counters (cross-zeroed)

// ---------------------------------------------------------------------------
__device__ __forceinline__ void gridbar(int id) {
    __syncthreads();
    if (threadIdx.x == 0) {
        __threadfence();
        atomicAdd((int*)&g_barcnt[id], 1);
        while (g_barcnt[id] < SB) { }
        __threadfence();
    }
    __syncthreads();
}

__device__ __forceinline__ uint32_t smem_u32(const void* p) {
    uint32_t a;
    asm("{ .reg .u64 t; cvta.to.shared.u64 t, %1; cvt.u32.u64 %0, t; }"
        : "=r"(a) : "l"(p));
    return a;
}

#define LDSM4(r, a)                                                            \
    asm volatile("ldmatrix.sync.aligned.m8n8.x4.shared.b16 {%0,%1,%2,%3}, [%4];" \
        : "=r"((r)[0]), "=r"((r)[1]), "=r"((r)[2]), "=r"((r)[3]) : "r"(a))

#define MMA16816(d, a, b0, b1)                                                 \
    asm volatile("mma.sync.aligned.m16n8k16.row.col.f32.bf16.bf16.f32 "        \
        "{%0,%1,%2,%3}, {%4,%5,%6,%7}, {%8,%9}, {%0,%1,%2,%3};"                \
        : "+f"((d)[0]), "+f"((d)[1]), "+f"((d)[2]), "+f"((d)[3])               \
        : "r"((a)[0]), "r"((a)[1]), "r"((a)[2]), "r"((a)[3]), "r"(b0), "r"(b1))

#define TS       136
#define SM_AV    0
#define SM_AHI   1024
#define SM_ALO   (1024 + 34816)
#define SM_BHI   (35840 + 34816)
#define SM_BLO   (70656 + 34816)
#define K1_SMEM  140288
#define SM_STAGE 1024
#define SSTR     132

// ---------------------------------------------------------------------------
__device__ __forceinline__ void load_edge(const void* edges, int e, int is64,
                                          int& src, int& dst) {
    if (is64) {
        const long long* p = (const long long*)edges;
        src = (int)p[3 * e];
        dst = (int)p[3 * e + 2];
    } else {
        const int* p = (const int*)edges;
        src = p[3 * e];
        dst = p[3 * e + 2];
    }
}

// ---------------------------------------------------------------------------
// ksort: zero -> histogram -> scan -> scatter, one kernel, grid barriers 0..3.
__global__ __launch_bounds__(256) void ksort(const void* __restrict__ edges,
                                             int N, int E) {
    __shared__ int ws[8];
    __shared__ int sbs[SB];
    const int tid = threadIdx.x, b = blockIdx.x;
    const int lane = tid & 31, wid = tid >> 5;
    const int gt = b * 256 + tid, GS = SB * 256;

    // P0: init
    if (gt == 0) {
        const unsigned int* e32 = (const unsigned int*)edges;
        int is64 = 1;
        #pragma unroll 1
        for (int j = 0; j < 32; j++)
            if (e32[2 * j + 1] != 0u) { is64 = 0; break; }
        g_is64 = is64;
        g_hsum[0] = g_hsum[1] = g_hsum[2] = g_hsum[3] = 0.f;
        g_start[N] = E;
        g_barcnt[4] = 0;                 // reset k35's barrier for this launch
    }
    for (int i = gt; i < N; i += GS) g_cnt[i] = 0;
    gridbar(0);

    const int is64 = *(volatile int*)&g_is64;

    // P1: histogram
    for (int e = gt; e < E; e += GS) {
        int s, d;
        load_edge(edges, e, is64, s, d);
        atomicAdd(&g_cnt[s], 1);
    }
    gridbar(1);

    // P2: per-block chunk scan (chunk <= 256)
    const int CH = (N + SB - 1) / SB;    // 136 for N=20000
    const int idx = b * CH + tid;
    int v = (tid < CH && idx < N) ? __ldcg(&g_cnt[idx]) : 0;
    int x = v;
    #pragma unroll
    for (int off = 1; off < 32; off <<= 1) {
        int t = __shfl_up_sync(0xffffffffu, x, off);
        if (lane >= off) x += t;
    }
    if (lane == 31) ws[wid] = x;
    __syncthreads();
    if (wid == 0 && lane < 8) {
        int y = ws[lane];
        #pragma unroll
        for (int off = 1; off < 8; off <<= 1) {
            int t = __shfl_up_sync(0xffu, y, off);
            if (lane >= off) y += t;
        }
        ws[lane] = y;
    }
    __syncthreads();
    int excl = x - v + (wid > 0 ? ws[wid - 1] : 0);
    if (tid == 0) g_bsum[b] = 0;         // ensure defined
    __syncthreads();
    if (tid == 0) g_bsum[b] = ws[7];
    gridbar(2);

    // P3: global prefix + write start/cursor
    if (tid < SB) sbs[tid] = __ldcg(&g_bsum[tid]);
    __syncthreads();
    int pre = 0;
    for (int j = 0; j < b; j++) pre += sbs[j];
    if (tid < CH && idx < N) {
        int st = excl + pre;
        g_start[idx] = st;
        g_cnt[idx]   = st;
    }
    gridbar(3);

    // P4: scatter
    for (int e = gt; e < E; e += GS) {
        int s, d;
        load_edge(edges, e, is64, s, d);
        int pos = atomicAdd(&g_cnt[s], 1);
        g_perm[pos] = make_int2(s, d);
    }
}

// ---------------------------------------------------------------------------
__device__ __forceinline__ void split_pack(float x, float y,
                                           uint32_t& hi, uint32_t& lo) {
    __nv_bfloat16 hx = __float2bfloat16(x), hy = __float2bfloat16(y);
    __nv_bfloat16 lx = __float2bfloat16(x - __bfloat162float(hx));
    __nv_bfloat16 ly = __float2bfloat16(y - __bfloat162float(hy));
    hi = ((uint32_t)*(unsigned short*)&hy << 16) | *(unsigned short*)&hx;
    lo = ((uint32_t)*(unsigned short*)&ly << 16) | *(unsigned short*)&lx;
}

// K1: HMMA bf16-split GEMM. CTA: 128 nodes x 128 cols (head = blockIdx.y).
__global__ __launch_bounds__(256) void k1_mma(const float* __restrict__ A,
                                              const float* __restrict__ Wt,
                                              const float* __restrict__ av,
                                              int N) {
    extern __shared__ char smem[];
    const uint32_t sbase = smem_u32(smem);
    const int h   = blockIdx.y;
    const int nb  = blockIdx.x * 128;
    const int tid = threadIdx.x;
    const int lane = tid & 31, wid = tid >> 5;

    float* sAv = (float*)(smem + SM_AV);
    if (tid < 256) sAv[tid] = av[h * 256 + tid];

    #pragma unroll
    for (int it = 0; it < 16; it++) {
        int g = it * 256 + tid;
        int row = g >> 5;
        int kq  = (g & 31) << 2;
        int n = nb + row;
        float4 v = make_float4(0.f, 0.f, 0.f, 0.f);
        if (n < N) v = *(const float4*)(A + (size_t)n * 128 + kq);
        uint32_t h0, l0, h1, l1;
        split_pack(v.x, v.y, h0, l0);
        split_pack(v.z, v.w, h1, l1);
        uint32_t off = (row * TS + kq) * 2;
        *(uint2*)(smem + SM_AHI + off) = make_uint2(h0, h1);
        *(uint2*)(smem + SM_ALO + off) = make_uint2(l0, l1);
    }
    #pragma unroll
    for (int it = 0; it < 16; it++) {
        int g = it * 256 + tid;
        int row = g >> 5;
        int kq  = (g & 31) << 2;
        float4 v = *(const float4*)(Wt + (size_t)(h * 128 + row) * 128 + kq);
        uint32_t h0, l0, h1, l1;
        split_pack(v.x, v.y, h0, l0);
        split_pack(v.z, v.w, h1, l1);
        uint32_t off = (row * TS + kq) * 2;
        *(uint2*)(smem + SM_BHI + off) = make_uint2(h0, h1);
        *(uint2*)(smem + SM_BLO + off) = make_uint2(l0, l1);
    }
    __syncthreads();

    const int m0 = (wid & 1) * 64;
    const int n0 = (wid >> 1) * 32;

    uint32_t offA[4], offB[2];
    {
        int rowA = m0 + (lane & 15);
        int colA = (lane >> 4) << 3;
        #pragma unroll
        for (int mi = 0; mi < 4; mi++)
            offA[mi] = ((rowA + mi * 16) * TS + colA) * 2;
        int nB = n0 + (lane & 7) + ((lane >> 4) << 3);
        int kB = ((lane >> 3) & 1) << 3;
        #pragma unroll
        for (int nbi = 0; nbi < 2; nbi++)
            offB[nbi] = ((nB + nbi * 16) * TS + kB) * 2;
    }

    float acc[4][4][4];
    #pragma unroll
    for (int mi = 0; mi < 4; mi++)
        #pragma unroll
        for (int ni = 0; ni < 4; ni++)
            #pragma unroll
            for (int q = 0; q < 4; q++) acc[mi][ni][q] = 0.f;

    const uint32_t aHi = sbase + SM_AHI, aLo = sbase + SM_ALO;
    const uint32_t bHi = sbase + SM_BHI, bLo = sbase + SM_BLO;

    #pragma unroll
    for (int ks = 0; ks < 8; ks++) {
        uint32_t AH[4][4], AL[4][4], BH[2][4], BL[2][4];
        #pragma unroll
        for (int mi = 0; mi < 4; mi++) {
            LDSM4(AH[mi], aHi + offA[mi] + ks * 32);
            LDSM4(AL[mi], aLo + offA[mi] + ks * 32);
        }
        #pragma unroll
        for (int nbi = 0; nbi < 2; nbi++) {
            LDSM4(BH[nbi], bHi + offB[nbi] + ks * 32);
            LDSM4(BL[nbi], bLo + offB[nbi] + ks * 32);
        }
        #pragma unroll
        for (int mi = 0; mi < 4; mi++)
            #pragma unroll
            for (int ni = 0; ni < 4; ni++) {
                int gsel = ni >> 1, p = (ni & 1) * 2;
                MMA16816(acc[mi][ni], AH[mi], BH[gsel][p], BH[gsel][p + 1]);
                MMA16816(acc[mi][ni], AH[mi], BL[gsel][p], BL[gsel][p + 1]);
                MMA16816(acc[mi][ni], AL[mi], BH[gsel][p], BH[gsel][p + 1]);
            }
    }

    __syncthreads();

    float* stage = (float*)(smem + SM_STAGE);
    {
        int r = m0 + (lane >> 2);
        int c = n0 + 2 * (lane & 3);
        #pragma unroll
        for (int mi = 0; mi < 4; mi++)
            #pragma unroll
            for (int ni = 0; ni < 4; ni++) {
                int rr = r + mi * 16, cc = c + ni * 8;
                *(float2*)&stage[rr * SSTR + cc] =
                    make_float2(acc[mi][ni][0], acc[mi][ni][1]);
                *(float2*)&stage[(rr + 8) * SSTR + cc] =
                    make_float2(acc[mi][ni][2], acc[mi][ni][3]);
            }
    }
    __syncthreads();

    if (tid < 128) {
        int n = nb + tid;
        if (n < N) {
            float s = 0.f, d = 0.f;
            #pragma unroll
            for (int j = 0; j < 32; j++) {
                float4 xv = *(float4*)&stage[tid * SSTR + j * 4];
                float4 as = *(float4*)&sAv[j * 4];
                float4 ad = *(float4*)&sAv[128 + j * 4];
                s = fmaf(xv.x, as.x, fmaf(xv.y, as.y,
                    fmaf(xv.z, as.z, fmaf(xv.w, as.w, s))));
                d = fmaf(xv.x, ad.x, fmaf(xv.y, ad.y,
                    fmaf(xv.z, ad.z, fmaf(xv.w, ad.w, d))));
            }
            g_sprm[n * 8 + h]     = s;
            g_sprm[n * 8 + 4 + h] = d;
        }
    }

    #pragma unroll
    for (int rr = 0; rr < 16; rr++) {
        int row = (tid >> 5) * 16 + rr;
        int n = nb + row;
        if (n < N) {
            float4 v = *(float4*)&stage[row * SSTR + lane * 4];
            size_t off = (size_t)n * 512 + h * 128 + lane * 4;
            *(float4*)(g_X + off) = v;
            __nv_fp8x2_storage_t p0 = __nv_cvt_float2_to_fp8x2(
                make_float2(v.x * 32.f, v.y * 32.f), __NV_SATFINITE, __NV_E4M3);
            __nv_fp8x2_storage_t p1 = __nv_cvt_float2_to_fp8x2(
                make_float2(v.z * 32.f, v.w * 32.f), __NV_SATFINITE, __NV_E4M3);
            uint32_t pk = (uint32_t)p0 | ((uint32_t)p1 << 16);
            *(uint32_t*)(g_Xf8 + off) = pk;
        }
    }
}

// ---------------------------------------------------------------------------
// k35: scores+sum (phase A) -> grid barrier 4 -> warp-per-node agg (phase B).
__global__ __launch_bounds__(256) void k35(float* __restrict__ out,
                                           int N, int E) {
    __shared__ float wsum[8][4];
    __shared__ float sZ[4];
    const int tid = threadIdx.x, b = blockIdx.x;
    const int lane = tid & 31, wid = tid >> 5;
    const int gt = b * 256 + tid, GS = SB * 256;

    if (b == 0 && tid == 0) {            // reset ksort's barriers for next launch
        g_barcnt[0] = 0; g_barcnt[1] = 0; g_barcnt[2] = 0; g_barcnt[3] = 0;
    }

    // phase A: probs + per-head sums
    float lp[4] = {0.f, 0.f, 0.f, 0.f};
    for (int i = gt; i < E; i += GS) {
        int2 sd = g_perm[i];
        float4 sv = *(const float4*)(g_sprm + sd.x * 8);
        float4 dv = *(const float4*)(g_sprm + sd.y * 8 + 4);
        float s0 = sv.x + dv.x, s1 = sv.y + dv.y;
        float s2 = sv.z + dv.z, s3 = sv.w + dv.w;
        s0 = s0 > 0.f ? s0 : 0.01f * s0;
        s1 = s1 > 0.f ? s1 : 0.01f * s1;
        s2 = s2 > 0.f ? s2 : 0.01f * s2;
        s3 = s3 > 0.f ? s3 : 0.01f * s3;
        float4 p4 = make_float4(__expf(s0), __expf(s1), __expf(s2), __expf(s3));
        *(float4*)(g_sc + (size_t)i * 4) = p4;
        lp[0] += p4.x; lp[1] += p4.y; lp[2] += p4.z; lp[3] += p4.w;
    }
    #pragma unroll
    for (int h = 0; h < 4; h++)
        #pragma unroll
        for (int off = 16; off > 0; off >>= 1)
            lp[h] += __shfl_xor_sync(0xffffffffu, lp[h], off);
    if (lane < 4) wsum[wid][lane] = lp[lane];
    __syncthreads();
    if (tid < 4) {
        float s = 0.f;
        #pragma unroll
        for (int w = 0; w < 8; w++) s += wsum[w][tid];
        atomicAdd(&g_hsum[tid], s);
    }
    gridbar(4);

    if (tid < 4)
        sZ[tid] = 0.25f / *(volatile float*)&g_hsum[tid] * (1.f / 32.f);
    __syncthreads();
    float z0 = sZ[0], z1 = sZ[1], z2 = sZ[2], z3 = sZ[3];

    // phase B: warp-per-node aggregation (grid-stride over nodes)
    for (int n = b * 8 + wid; n < N; n += SB * 8) {
        int s = g_start[n], eend = g_start[n + 1];
        float4 acc = make_float4(0.f, 0.f, 0.f, 0.f);
        for (int i = s; i < eend; i++) {
            int dst = g_perm[i].y;
            float4 wv = __ldcg((const float4*)(g_sc + (size_t)i * 4));
            float w[4] = {wv.x * z0, wv.y * z1, wv.z * z2, wv.w * z3};
            const uint8_t* xp = g_Xf8 + (size_t)dst * 512;
            #pragma unroll
            for (int h = 0; h < 4; h++) {
                uint32_t raw = *(const uint32_t*)(xp + h * 128 + lane * 4);
                __half2_raw r0 = __nv_cvt_fp8x2_to_halfraw2(
                    (__nv_fp8x2_storage_t)(raw & 0xffff), __NV_E4M3);
                __half2_raw r1 = __nv_cvt_fp8x2_to_halfraw2(
                    (__nv_fp8x2_storage_t)(raw >> 16), __NV_E4M3);
                float2 f0 = __half22float2(*(__half2*)&r0);
                float2 f1 = __half22float2(*(__half2*)&r1);
                acc.x = fmaf(w[h], f0.x, acc.x);
                acc.y = fmaf(w[h], f0.y, acc.y);
                acc.z = fmaf(w[h], f1.x, acc.z);
                acc.w = fmaf(w[h], f1.y, acc.w);
            }
        }
        const float4* xv = (const float4*)g_X + (size_t)n * 128;
        float4 m0 = xv[lane], m1 = xv[32 + lane];
        float4 m2 = xv[64 + lane], m3 = xv[96 + lane];
        float4 r;
        r.x = fmaf(0.25f, m0.x + m1.x + m2.x + m3.x, acc.x);
        r.y = fmaf(0.25f, m0.y + m1.y + m2.y + m3.y, acc.y);
        r.z = fmaf(0.25f, m0.z + m1.z + m2.z + m3.z, acc.z);
        r.w = fmaf(0.25f, m0.w + m1.w + m2.w + m3.w, acc.w);
        ((float4*)out)[(size_t)n * 32 + lane] = r;
    }
}

// ---------------------------------------------------------------------------
extern "C" void kernel_launch(void* const* d_in, const int* in_sizes, int n_in,
                              void* d_out, int out_size) {
    const float* input_h = (const float*)d_in[0];
    const void*  edges   = d_in[1];
    const float* W       = (const float*)d_in[2];
    const float* a       = (const float*)d_in[3];
    float* out = (float*)d_out;

    int N = in_sizes[0] / 128;   // 20000
    int E = in_sizes[1] / 3;     // 320000

    cudaFuncSetAttribute(k1_mma, cudaFuncAttributeMaxDynamicSharedMemorySize,
                         K1_SMEM);

    ksort<<<SB, 256>>>(edges, N, E);

    dim3 g1((N + 127) / 128, 4);
    k1_mma<<<g1, 256, K1_SMEM>>>(input_h, W, a, N);

    k35<<<SB, 256>>>(out, N, E);
}

// round 11
// speedup vs baseline: 1.4247x; 1.4247x over previous
#include <cuda_runtime.h>
#include <cuda_fp16.h>
#include <cuda_bf16.h>
#include <cuda_fp8.h>
#include <cstdint>

#define NMAX 20000
#define EMAX 320000
#define SB   148            // grid-resident block count
#define BT   1024           // threads per persistent block (32 warps)

__device__ float   g_X[NMAX * 512];      // fp32 X[n][h*128+o] (head-mean)
__device__ uint8_t g_Xf8[NMAX * 512];    // e4m3 (x*32) copy for gathers
__device__ float   g_sprm[NMAX * 8];     // [n*8+h]=s_src, [n*8+4+h]=s_dst
__device__ float   g_sc[EMAX * 4];       // exp(score), slot-major float4
__device__ int2    g_perm[EMAX];         // sorted-by-src {src, dst}
__device__ int     g_cnt[NMAX];          // histogram -> cursor
__device__ int     g_start[NMAX + 1];    // bucket starts
__device__ int     g_bsum[SB];           // per-block sums for scan
__device__ float   g_hsum[4];
__device__ int     g_is64;
__device__ volatile int g_barcnt[8];     // spin-barrier counters (cross-zeroed)

// ---------------------------------------------------------------------------
__device__ __forceinline__ void gridbar(int id) {
    __syncthreads();
    if (threadIdx.x == 0) {
        __threadfence();
        atomicAdd((int*)&g_barcnt[id], 1);
        while (g_barcnt[id] < SB) { }
        __threadfence();
    }
    __syncthreads();
}

__device__ __forceinline__ uint32_t smem_u32(const void* p) {
    uint32_t a;
    asm("{ .reg .u64 t; cvta.to.shared.u64 t, %1; cvt.u32.u64 %0, t; }"
        : "=r"(a) : "l"(p));
    return a;
}

#define LDSM4(r, a)                                                            \
    asm volatile("ldmatrix.sync.aligned.m8n8.x4.shared.b16 {%0,%1,%2,%3}, [%4];" \
        : "=r"((r)[0]), "=r"((r)[1]), "=r"((r)[2]), "=r"((r)[3]) : "r"(a))

#define MMA16816(d, a, b0, b1)                                                 \
    asm volatile("mma.sync.aligned.m16n8k16.row.col.f32.bf16.bf16.f32 "        \
        "{%0,%1,%2,%3}, {%4,%5,%6,%7}, {%8,%9}, {%0,%1,%2,%3};"                \
        : "+f"((d)[0]), "+f"((d)[1]), "+f"((d)[2]), "+f"((d)[3])               \
        : "r"((a)[0]), "r"((a)[1]), "r"((a)[2]), "r"((a)[3]), "r"(b0), "r"(b1))

#define TS       136
#define SM_AV    0
#define SM_AHI   1024
#define SM_ALO   (1024 + 34816)
#define SM_BHI   (35840 + 34816)
#define SM_BLO   (70656 + 34816)
#define K1_SMEM  140288
#define SM_STAGE 1024
#define SSTR     132

// ---------------------------------------------------------------------------
__device__ __forceinline__ void load_edge(const void* edges, int e, int is64,
                                          int& src, int& dst) {
    if (is64) {
        const long long* p = (const long long*)edges;
        src = (int)p[3 * e];
        dst = (int)p[3 * e + 2];
    } else {
        const int* p = (const int*)edges;
        src = p[3 * e];
        dst = p[3 * e + 2];
    }
}

// ---------------------------------------------------------------------------
// ksort: zero -> histogram -> scan -> scatter, one kernel, grid barriers 0..3.
__global__ __launch_bounds__(BT) void ksort(const void* __restrict__ edges,
                                            int N, int E) {
    __shared__ int ws[32];
    __shared__ int sbs[SB];
    const int tid = threadIdx.x, b = blockIdx.x;
    const int lane = tid & 31, wid = tid >> 5;
    const int gt = b * BT + tid, GS = SB * BT;

    // P0: init
    if (gt == 0) {
        const unsigned int* e32 = (const unsigned int*)edges;
        int is64 = 1;
        #pragma unroll 1
        for (int j = 0; j < 32; j++)
            if (e32[2 * j + 1] != 0u) { is64 = 0; break; }
        g_is64 = is64;
        g_hsum[0] = g_hsum[1] = g_hsum[2] = g_hsum[3] = 0.f;
        g_start[N] = E;
        g_barcnt[4] = 0;                 // reset k35's barrier for this launch
    }
    for (int i = gt; i < N; i += GS) g_cnt[i] = 0;
    gridbar(0);

    const int is64 = *(volatile int*)&g_is64;

    // P1: histogram
    for (int e = gt; e < E; e += GS) {
        int s, d;
        load_edge(edges, e, is64, s, d);
        atomicAdd(&g_cnt[s], 1);
    }
    gridbar(1);

    // P2: per-block chunk scan (chunk CH <= 256 <= BT)
    const int CH = (N + SB - 1) / SB;    // 136 for N=20000
    const int idx = b * CH + tid;
    int v = (tid < CH && idx < N) ? __ldcg(&g_cnt[idx]) : 0;
    int x = v;
    #pragma unroll
    for (int off = 1; off < 32; off <<= 1) {
        int t = __shfl_up_sync(0xffffffffu, x, off);
        if (lane >= off) x += t;
    }
    if (lane == 31) ws[wid] = x;
    __syncthreads();
    if (wid == 0) {
        int y = ws[lane];
        #pragma unroll
        for (int off = 1; off < 32; off <<= 1) {
            int t = __shfl_up_sync(0xffffffffu, y, off);
            if (lane >= off) y += t;
        }
        ws[lane] = y;
    }
    __syncthreads();
    int excl = x - v + (wid > 0 ? ws[wid - 1] : 0);
    if (tid == 0) g_bsum[b] = ws[31];
    gridbar(2);

    // P3: global prefix + write start/cursor
    if (tid < SB) sbs[tid] = __ldcg(&g_bsum[tid]);
    __syncthreads();
    int pre = 0;
    for (int j = 0; j < b; j++) pre += sbs[j];
    if (tid < CH && idx < N) {
        int st = excl + pre;
        g_start[idx] = st;
        g_cnt[idx]   = st;
    }
    gridbar(3);

    // P4: scatter
    for (int e = gt; e < E; e += GS) {
        int s, d;
        load_edge(edges, e, is64, s, d);
        int pos = atomicAdd(&g_cnt[s], 1);
        g_perm[pos] = make_int2(s, d);
    }
}

// ---------------------------------------------------------------------------
__device__ __forceinline__ void split_pack(float x, float y,
                                           uint32_t& hi, uint32_t& lo) {
    __nv_bfloat16 hx = __float2bfloat16(x), hy = __float2bfloat16(y);
    __nv_bfloat16 lx = __float2bfloat16(x - __bfloat162float(hx));
    __nv_bfloat16 ly = __float2bfloat16(y - __bfloat162float(hy));
    hi = ((uint32_t)*(unsigned short*)&hy << 16) | *(unsigned short*)&hx;
    lo = ((uint32_t)*(unsigned short*)&ly << 16) | *(unsigned short*)&lx;
}

// K1: HMMA bf16-split GEMM. CTA: 128 nodes x 128 cols (head = blockIdx.y).
__global__ __launch_bounds__(256) void k1_mma(const float* __restrict__ A,
                                              const float* __restrict__ Wt,
                                              const float* __restrict__ av,
                                              int N) {
    extern __shared__ char smem[];
    const uint32_t sbase = smem_u32(smem);
    const int h   = blockIdx.y;
    const int nb  = blockIdx.x * 128;
    const int tid = threadIdx.x;
    const int lane = tid & 31, wid = tid >> 5;

    float* sAv = (float*)(smem + SM_AV);
    if (tid < 256) sAv[tid] = av[h * 256 + tid];

    #pragma unroll
    for (int it = 0; it < 16; it++) {
        int g = it * 256 + tid;
        int row = g >> 5;
        int kq  = (g & 31) << 2;
        int n = nb + row;
        float4 v = make_float4(0.f, 0.f, 0.f, 0.f);
        if (n < N) v = *(const float4*)(A + (size_t)n * 128 + kq);
        uint32_t h0, l0, h1, l1;
        split_pack(v.x, v.y, h0, l0);
        split_pack(v.z, v.w, h1, l1);
        uint32_t off = (row * TS + kq) * 2;
        *(uint2*)(smem + SM_AHI + off) = make_uint2(h0, h1);
        *(uint2*)(smem + SM_ALO + off) = make_uint2(l0, l1);
    }
    #pragma unroll
    for (int it = 0; it < 16; it++) {
        int g = it * 256 + tid;
        int row = g >> 5;
        int kq  = (g & 31) << 2;
        float4 v = *(const float4*)(Wt + (size_t)(h * 128 + row) * 128 + kq);
        uint32_t h0, l0, h1, l1;
        split_pack(v.x, v.y, h0, l0);
        split_pack(v.z, v.w, h1, l1);
        uint32_t off = (row * TS + kq) * 2;
        *(uint2*)(smem + SM_BHI + off) = make_uint2(h0, h1);
        *(uint2*)(smem + SM_BLO + off) = make_uint2(l0, l1);
    }
    __syncthreads();

    const int m0 = (wid & 1) * 64;
    const int n0 = (wid >> 1) * 32;

    uint32_t offA[4], offB[2];
    {
        int rowA = m0 + (lane & 15);
        int colA = (lane >> 4) << 3;
        #pragma unroll
        for (int mi = 0; mi < 4; mi++)
            offA[mi] = ((rowA + mi * 16) * TS + colA) * 2;
        int nB = n0 + (lane & 7) + ((lane >> 4) << 3);
        int kB = ((lane >> 3) & 1) << 3;
        #pragma unroll
        for (int nbi = 0; nbi < 2; nbi++)
            offB[nbi] = ((nB + nbi * 16) * TS + kB) * 2;
    }

    float acc[4][4][4];
    #pragma unroll
    for (int mi = 0; mi < 4; mi++)
        #pragma unroll
        for (int ni = 0; ni < 4; ni++)
            #pragma unroll
            for (int q = 0; q < 4; q++) acc[mi][ni][q] = 0.f;

    const uint32_t aHi = sbase + SM_AHI, aLo = sbase + SM_ALO;
    const uint32_t bHi = sbase + SM_BHI, bLo = sbase + SM_BLO;

    #pragma unroll
    for (int ks = 0; ks < 8; ks++) {
        uint32_t AH[4][4], AL[4][4], BH[2][4], BL[2][4];
        #pragma unroll
        for (int mi = 0; mi < 4; mi++) {
            LDSM4(AH[mi], aHi + offA[mi] + ks * 32);
            LDSM4(AL[mi], aLo + offA[mi] + ks * 32);
        }
        #pragma unroll
        for (int nbi = 0; nbi < 2; nbi++) {
            LDSM4(BH[nbi], bHi + offB[nbi] + ks * 32);
            LDSM4(BL[nbi], bLo + offB[nbi] + ks * 32);
        }
        #pragma unroll
        for (int mi = 0; mi < 4; mi++)
            #pragma unroll
            for (int ni = 0; ni < 4; ni++) {
                int gsel = ni >> 1, p = (ni & 1) * 2;
                MMA16816(acc[mi][ni], AH[mi], BH[gsel][p], BH[gsel][p + 1]);
                MMA16816(acc[mi][ni], AH[mi], BL[gsel][p], BL[gsel][p + 1]);
                MMA16816(acc[mi][ni], AL[mi], BH[gsel][p], BH[gsel][p + 1]);
            }
    }

    __syncthreads();

    float* stage = (float*)(smem + SM_STAGE);
    {
        int r = m0 + (lane >> 2);
        int c = n0 + 2 * (lane & 3);
        #pragma unroll
        for (int mi = 0; mi < 4; mi++)
            #pragma unroll
            for (int ni = 0; ni < 4; ni++) {
                int rr = r + mi * 16, cc = c + ni * 8;
                *(float2*)&stage[rr * SSTR + cc] =
                    make_float2(acc[mi][ni][0], acc[mi][ni][1]);
                *(float2*)&stage[(rr + 8) * SSTR + cc] =
                    make_float2(acc[mi][ni][2], acc[mi][ni][3]);
            }
    }
    __syncthreads();

    if (tid < 128) {
        int n = nb + tid;
        if (n < N) {
            float s = 0.f, d = 0.f;
            #pragma unroll
            for (int j = 0; j < 32; j++) {
                float4 xv = *(float4*)&stage[tid * SSTR + j * 4];
                float4 as = *(float4*)&sAv[j * 4];
                float4 ad = *(float4*)&sAv[128 + j * 4];
                s = fmaf(xv.x, as.x, fmaf(xv.y, as.y,
                    fmaf(xv.z, as.z, fmaf(xv.w, as.w, s))));
                d = fmaf(xv.x, ad.x, fmaf(xv.y, ad.y,
                    fmaf(xv.z, ad.z, fmaf(xv.w, ad.w, d))));
            }
            g_sprm[n * 8 + h]     = s;
            g_sprm[n * 8 + 4 + h] = d;
        }
    }

    #pragma unroll
    for (int rr = 0; rr < 16; rr++) {
        int row = (tid >> 5) * 16 + rr;
        int n = nb + row;
        if (n < N) {
            float4 v = *(float4*)&stage[row * SSTR + lane * 4];
            size_t off = (size_t)n * 512 + h * 128 + lane * 4;
            *(float4*)(g_X + off) = v;
            __nv_fp8x2_storage_t p0 = __nv_cvt_float2_to_fp8x2(
                make_float2(v.x * 32.f, v.y * 32.f), __NV_SATFINITE, __NV_E4M3);
            __nv_fp8x2_storage_t p1 = __nv_cvt_float2_to_fp8x2(
                make_float2(v.z * 32.f, v.w * 32.f), __NV_SATFINITE, __NV_E4M3);
            uint32_t pk = (uint32_t)p0 | ((uint32_t)p1 << 16);
            *(uint32_t*)(g_Xf8 + off) = pk;
        }
    }
}

// ---------------------------------------------------------------------------
// k35: scores+sum (phase A) -> grid barrier 4 -> warp-per-node agg (phase B).
__global__ __launch_bounds__(BT) void k35(float* __restrict__ out,
                                          int N, int E) {
    __shared__ float wsum[32][4];
    __shared__ float sZ[4];
    const int tid = threadIdx.x, b = blockIdx.x;
    const int lane = tid & 31, wid = tid >> 5;
    const int gt = b * BT + tid, GS = SB * BT;

    if (b == 0 && tid == 0) {            // reset ksort's barriers for next launch
        g_barcnt[0] = 0; g_barcnt[1] = 0; g_barcnt[2] = 0; g_barcnt[3] = 0;
    }

    // phase A: probs + per-head sums
    float lp[4] = {0.f, 0.f, 0.f, 0.f};
    for (int i = gt; i < E; i += GS) {
        int2 sd = g_perm[i];
        float4 sv = *(const float4*)(g_sprm + sd.x * 8);
        float4 dv = *(const float4*)(g_sprm + sd.y * 8 + 4);
        float s0 = sv.x + dv.x, s1 = sv.y + dv.y;
        float s2 = sv.z + dv.z, s3 = sv.w + dv.w;
        s0 = s0 > 0.f ? s0 : 0.01f * s0;
        s1 = s1 > 0.f ? s1 : 0.01f * s1;
        s2 = s2 > 0.f ? s2 : 0.01f * s2;
        s3 = s3 > 0.f ? s3 : 0.01f * s3;
        float4 p4 = make_float4(__expf(s0), __expf(s1), __expf(s2), __expf(s3));
        *(float4*)(g_sc + (size_t)i * 4) = p4;
        lp[0] += p4.x; lp[1] += p4.y; lp[2] += p4.z; lp[3] += p4.w;
    }
    #pragma unroll
    for (int h = 0; h < 4; h++)
        #pragma unroll
        for (int off = 16; off > 0; off >>= 1)
            lp[h] += __shfl_xor_sync(0xffffffffu, lp[h], off);
    if (lane < 4) wsum[wid][lane] = lp[lane];
    __syncthreads();
    if (tid < 4) {
        float s = 0.f;
        #pragma unroll
        for (int w = 0; w < 32; w++) s += wsum[w][tid];
        atomicAdd(&g_hsum[tid], s);
    }
    gridbar(4);

    if (tid < 4)
        sZ[tid] = 0.25f / *(volatile float*)&g_hsum[tid] * (1.f / 32.f);
    __syncthreads();
    float z0 = sZ[0], z1 = sZ[1], z2 = sZ[2], z3 = sZ[3];

    // phase B: warp-per-node aggregation (grid-stride over nodes, 32 warps/blk)
    for (int n = b * 32 + wid; n < N; n += SB * 32) {
        int s = g_start[n], eend = g_start[n + 1];
        float4 acc = make_float4(0.f, 0.f, 0.f, 0.f);
        for (int i = s; i < eend; i++) {
            int dst = g_perm[i].y;
            float4 wv = __ldcg((const float4*)(g_sc + (size_t)i * 4));
            float w[4] = {wv.x * z0, wv.y * z1, wv.z * z2, wv.w * z3};
            const uint8_t* xp = g_Xf8 + (size_t)dst * 512;
            #pragma unroll
            for (int h = 0; h < 4; h++) {
                uint32_t raw = *(const uint32_t*)(xp + h * 128 + lane * 4);
                __half2_raw r0 = __nv_cvt_fp8x2_to_halfraw2(
                    (__nv_fp8x2_storage_t)(raw & 0xffff), __NV_E4M3);
                __half2_raw r1 = __nv_cvt_fp8x2_to_halfraw2(
                    (__nv_fp8x2_storage_t)(raw >> 16), __NV_E4M3);
                float2 f0 = __half22float2(*(__half2*)&r0);
                float2 f1 = __half22float2(*(__half2*)&r1);
                acc.x = fmaf(w[h], f0.x, acc.x);
                acc.y = fmaf(w[h], f0.y, acc.y);
                acc.z = fmaf(w[h], f1.x, acc.z);
                acc.w = fmaf(w[h], f1.y, acc.w);
            }
        }
        const float4* xv = (const float4*)g_X + (size_t)n * 128;
        float4 m0 = xv[lane], m1 = xv[32 + lane];
        float4 m2 = xv[64 + lane], m3 = xv[96 + lane];
        float4 r;
        r.x = fmaf(0.25f, m0.x + m1.x + m2.x + m3.x, acc.x);
        r.y = fmaf(0.25f, m0.y + m1.y + m2.y + m3.y, acc.y);
        r.z = fmaf(0.25f, m0.z + m1.z + m2.z + m3.z, acc.z);
        r.w = fmaf(0.25f, m0.w + m1.w + m2.w + m3.w, acc.w);
        ((float4*)out)[(size_t)n * 32 + lane] = r;
    }
}

// ---------------------------------------------------------------------------
extern "C" void kernel_launch(void* const* d_in, const int* in_sizes, int n_in,
                              void* d_out, int out_size) {
    const float* input_h = (const float*)d_in[0];
    const void*  edges   = d_in[1];
    const float* W       = (const float*)d_in[2];
    const float* a       = (const float*)d_in[3];
    float* out = (float*)d_out;

    int N = in_sizes[0] / 128;   // 20000
    int E = in_sizes[1] / 3;     // 320000

    cudaFuncSetAttribute(k1_mma, cudaFuncAttributeMaxDynamicSharedMemorySize,
                         K1_SMEM);

    ksort<<<SB, BT>>>(edges, N, E);

    dim3 g1((N + 127) / 128, 4);
    k1_mma<<<g1, 256, K1_SMEM>>>(input_h, W, a, N);

    k35<<<SB, BT>>>(out, N, E);
}